// round 7
// baseline (speedup 1.0000x reference)
#include <cuda_runtime.h>
#include <math.h>

#define NBLK 1184u           // 148 SMs * 8 blocks — exactly one wave
#define NTHR 256u
#define TOTAL_TILES 2097152u // 16 * 2^20 spatial / 8 elems per tile

// Per-batch params (prob space), built once per block into smem:
//  P = {ab, c, Qh, Ql}:  ab = exp(lab[t-1]),  c = 0.5*exp(l1ab[t-1])
//  Qh = exp(logaddexp(la[t], l1a[t]-ln2)) = alpha + (1-alpha)/2   (x_t "hit")
//  Ql = 1e-30*alpha + (1-alpha)/2                                  (x_t "miss")
//  t==0: flag set; posterior = normalize(log_x_0 + one_step) in log space.

__global__ void __launch_bounds__(NTHR) qpost_kernel(const float* __restrict__ xt,
                                                     const float* __restrict__ x0,
                                                     float* __restrict__ out,
                                                     const int* __restrict__ t_raw,
                                                     const float* __restrict__ la,
                                                     const float* __restrict__ l1a,
                                                     const float* __restrict__ lab,
                                                     const float* __restrict__ l1ab) {
    __shared__ float4 sPar[16];
    __shared__ float2 sLog[16];   // log-space {q_hi, q_lo} for the t==0 path
    __shared__ int    sT0[16];

    if (threadIdx.x < 16) {
        int b = threadIdx.x;
        // int64-vs-int32 layout sniff (t in [0,1000); int64 LE high words = 0)
        bool is64 = true;
        #pragma unroll
        for (int i = 0; i < 8; i++)
            if (t_raw[2 * i + 1] != 0) { is64 = false; break; }
        int t = is64 ? t_raw[2 * b] : t_raw[b];

        float alpha = expf(la[t]);
        float oma   = expf(l1a[t]);             // = 1 - alpha (+1e-40)
        float Qh = alpha + 0.5f * oma;
        float Ql = 1e-30f * alpha + 0.5f * oma;
        float ab, c; int t0;
        if (t == 0) { t0 = 1; ab = 1.0f; c = 0.0f; }
        else { t0 = 0; ab = expf(lab[t - 1]); c = 0.5f * expf(l1ab[t - 1]); }
        sPar[b] = make_float4(ab, c, Qh, Ql);
        sLog[b] = make_float2(logf(Qh), logf(Ql));
        sT0[b]  = t0;
    }
    __syncthreads();

    const size_t cstr = (size_t)1 << 20;        // class stride
    const unsigned stride = NBLK * NTHR;        // tiles per grid pass

    unsigned i = blockIdx.x * NTHR + threadIdx.x;

    // ---- prologue: load tile i ----
    size_t e    = (size_t)i << 3;
    unsigned b  = (unsigned)(e >> 20);
    size_t base = ((size_t)b << 21) + (e & (cstr - 1));

    float4 cxA = __ldcs((const float4*)(xt + base));
    float4 cxB = __ldcs((const float4*)(xt + base + 4));
    float4 c0A = __ldcs((const float4*)(x0 + base));
    float4 c0B = __ldcs((const float4*)(x0 + base + 4));

    for (;;) {
        // ---- prefetch next tile (keeps DRAM busy under compute) ----
        unsigned ni = i + stride;
        bool have = (ni < TOTAL_TILES);
        float4 nxA, nxB, n0A, n0B;
        size_t nbase = 0; unsigned nb = 0;
        if (have) {
            size_t ne = (size_t)ni << 3;
            nb    = (unsigned)(ne >> 20);
            nbase = ((size_t)nb << 21) + (ne & (cstr - 1));
            nxA = __ldcs((const float4*)(xt + nbase));
            nxB = __ldcs((const float4*)(xt + nbase + 4));
            n0A = __ldcs((const float4*)(x0 + nbase));
            n0B = __ldcs((const float4*)(x0 + nbase + 4));
        }

        // ---- compute current tile ----
        float4 P = sPar[b];
        float4 oa0, oa1, ob0, ob1;

        if (!sT0[b]) {
            float abc = P.x + P.y;
            #pragma unroll
            for (int k = 0; k < 8; k++) {
                float x00 = (k < 4) ? ((const float*)&c0A)[k] : ((const float*)&c0B)[k - 4];
                float xtv = (k < 4) ? ((const float*)&cxA)[k] : ((const float*)&cxB)[k - 4];
                float e0 = __expf(x00);              // exp(x01) = 1 - e0 (K=2 log_softmax)
                float f0 = fmaf(P.x, e0, P.y);       // ab*e0 + c
                float f1 = fmaf(-P.x, e0, abc);      // ab*(1-e0) + c
                bool hi = (xtv > -1.0f);             // x_t one-hot hit on class 0?
                float w0 = f0 * (hi ? P.z : P.w);
                float w1 = f1 * (hi ? P.w : P.z);
                float r = __fdividef(1.0f, w0 + w1);
                float v0 = __logf(w0 * r);
                float v1 = __logf(w1 * r);
                if (k < 4) { ((float*)&oa0)[k] = v0; ((float*)&oa1)[k] = v1; }
                else       { ((float*)&ob0)[k - 4] = v0; ((float*)&ob1)[k - 4] = v1; }
            }
        } else {
            // t==0: posterior mean is log_x_0 itself; need true class-1 values
            float2 L = sLog[b];
            float4 c1A = __ldcs((const float4*)(x0 + base + cstr));
            float4 c1B = __ldcs((const float4*)(x0 + base + cstr + 4));
            #pragma unroll
            for (int k = 0; k < 8; k++) {
                float x00 = (k < 4) ? ((const float*)&c0A)[k] : ((const float*)&c0B)[k - 4];
                float x01 = (k < 4) ? ((const float*)&c1A)[k] : ((const float*)&c1B)[k - 4];
                float xtv = (k < 4) ? ((const float*)&cxA)[k] : ((const float*)&cxB)[k - 4];
                bool hi = (xtv > -1.0f);
                float u0 = x00 + (hi ? L.x : L.y);
                float u1 = x01 + (hi ? L.y : L.x);
                float m = fmaxf(u0, u1);
                float l = m + __logf(1.0f + __expf(fminf(u0, u1) - m));
                float v0 = u0 - l, v1 = u1 - l;
                if (k < 4) { ((float*)&oa0)[k] = v0; ((float*)&oa1)[k] = v1; }
                else       { ((float*)&ob0)[k - 4] = v0; ((float*)&ob1)[k - 4] = v1; }
            }
        }

        __stcs((float4*)(out + base),            oa0);
        __stcs((float4*)(out + base + 4),        ob0);
        __stcs((float4*)(out + base + cstr),     oa1);
        __stcs((float4*)(out + base + cstr + 4), ob1);

        if (!have) break;
        i = ni; b = nb; base = nbase;
        cxA = nxA; cxB = nxB; c0A = n0A; c0B = n0B;
    }
}

extern "C" void kernel_launch(void* const* d_in, const int* in_sizes, int n_in,
                              void* d_out, int out_size) {
    const float* log_x_t = (const float*)d_in[0];
    const float* log_x_0 = (const float*)d_in[1];
    const float* la      = (const float*)d_in[2];
    const float* l1a     = (const float*)d_in[3];
    const float* lab     = (const float*)d_in[4];
    const float* l1ab    = (const float*)d_in[5];
    const int*   t_raw   = (const int*)d_in[6];

    qpost_kernel<<<NBLK, NTHR>>>(log_x_t, log_x_0, (float*)d_out,
                                 t_raw, la, l1a, lab, l1ab);
}

// round 8
// speedup vs baseline: 1.0006x; 1.0006x over previous
#include <cuda_runtime.h>
#include <math.h>

// Per-thread cheap prob-space params (all schedule loads are L1 broadcast hits):
//  ab = exp(log_alpha_bars[t-1]),  c = 0.5*exp(log_1m_alpha_bars[t-1])
//  Qh = alpha + (1-alpha)/2   (x_t one-hot "hit" class),  alpha = exp(la[t])
//  Ql = 1e-30*alpha + (1-alpha)/2                        (x_t "miss" class)
// posterior_k ∝ (ab*p0_k + c) * Q_k ; normalize with rcp, back to log.
// t==0 (uniform per block): posterior = normalize(log_x_0 + one_step) in log space.

__device__ __forceinline__ void quad(float4 xq, float4 pq,
                                     float ab, float c, float abc,
                                     float Qh, float Ql,
                                     float4& o0, float4& o1) {
    #pragma unroll
    for (int k = 0; k < 4; k++) {
        float x00 = ((const float*)&pq)[k];
        float xtv = ((const float*)&xq)[k];
        float e0 = __expf(x00);              // exp(x01) = 1 - e0 (K=2 log_softmax)
        float f0 = fmaf(ab, e0, c);          // ab*e0 + c
        float f1 = fmaf(-ab, e0, abc);       // ab*(1-e0) + c
        bool hi = (xtv > -1.0f);             // x_t one-hot: 0 vs log(1e-30)
        float w0 = f0 * (hi ? Qh : Ql);
        float w1 = f1 * (hi ? Ql : Qh);
        float r = __fdividef(1.0f, w0 + w1);
        ((float*)&o0)[k] = __logf(w0 * r);
        ((float*)&o1)[k] = __logf(w1 * r);
    }
}

__global__ void __launch_bounds__(256) qpost_kernel(const float* __restrict__ xt,
                                                    const float* __restrict__ x0,
                                                    float* __restrict__ out,
                                                    const int* __restrict__ t_raw,
                                                    const float* __restrict__ la,
                                                    const float* __restrict__ l1a,
                                                    const float* __restrict__ lab,
                                                    const float* __restrict__ l1ab) {
    unsigned tid = blockIdx.x * 256u + threadIdx.x;
    size_t e = (size_t)tid << 3;                   // 8 spatial elems per thread
    unsigned b = (unsigned)(e >> 20);              // batch (uniform per block)
    size_t base = ((size_t)b << 21) + (e & (((size_t)1 << 20) - 1));
    const size_t cstr = (size_t)1 << 20;           // class stride

    // ---- front-batched streaming loads (MLP=4, independent of params) ----
    float4 xtA = __ldcs((const float4*)(xt + base));
    float4 xtB = __ldcs((const float4*)(xt + base + 4));
    float4 x0A = __ldcs((const float4*)(x0 + base));
    float4 x0B = __ldcs((const float4*)(x0 + base + 4));

    // ---- lean per-thread params, overlapped with load latency ----
    // int64-vs-int32 layout sniff (t in [0,1000); int64 LE high words all 0)
    int hw = 0;
    #pragma unroll
    for (int i = 0; i < 8; i++) hw |= __ldg(&t_raw[2 * i + 1]);
    int t = (hw == 0) ? __ldg(&t_raw[2 * b]) : __ldg(&t_raw[b]);

    float alpha = __expf(__ldg(&la[t]));
    float oma   = __expf(__ldg(&l1a[t]));          // 1 - alpha (+1e-40)
    float Qh = fmaf(0.5f, oma, alpha);
    float Ql = fmaf(0.5f, oma, 1e-30f * alpha);

    if (t != 0) {
        float ab = __expf(__ldg(&lab[t - 1]));
        float c  = 0.5f * __expf(__ldg(&l1ab[t - 1]));
        float abc = ab + c;

        float4 o0, o1;
        quad(xtA, x0A, ab, c, abc, Qh, Ql, o0, o1);
        __stcs((float4*)(out + base),        o0);
        __stcs((float4*)(out + base + cstr), o1);
        quad(xtB, x0B, ab, c, abc, Qh, Ql, o0, o1);
        __stcs((float4*)(out + base + 4),        o0);
        __stcs((float4*)(out + base + cstr + 4), o1);
    } else {
        // t==0 (rare; uniform per block): posterior mean = log_x_0 exactly,
        // need true class-1 values; stay in log space.
        float Lh = __logf(Qh);
        float Ll = __logf(Ql);
        float4 x1A = __ldcs((const float4*)(x0 + base + cstr));
        float4 x1B = __ldcs((const float4*)(x0 + base + cstr + 4));

        #pragma unroll
        for (int h = 0; h < 2; h++) {
            float4 xq = h ? xtB : xtA;
            float4 p0 = h ? x0B : x0A;
            float4 p1 = h ? x1B : x1A;
            float4 o0, o1;
            #pragma unroll
            for (int k = 0; k < 4; k++) {
                bool hi = (((const float*)&xq)[k] > -1.0f);
                float u0 = ((const float*)&p0)[k] + (hi ? Lh : Ll);
                float u1 = ((const float*)&p1)[k] + (hi ? Ll : Lh);
                float m = fmaxf(u0, u1);
                float l = m + __logf(1.0f + __expf(fminf(u0, u1) - m));
                ((float*)&o0)[k] = u0 - l;
                ((float*)&o1)[k] = u1 - l;
            }
            __stcs((float4*)(out + base + 4 * h),        o0);
            __stcs((float4*)(out + base + cstr + 4 * h), o1);
        }
    }
}

extern "C" void kernel_launch(void* const* d_in, const int* in_sizes, int n_in,
                              void* d_out, int out_size) {
    const float* log_x_t = (const float*)d_in[0];
    const float* log_x_0 = (const float*)d_in[1];
    const float* la      = (const float*)d_in[2];
    const float* l1a     = (const float*)d_in[3];
    const float* lab     = (const float*)d_in[4];
    const float* l1ab    = (const float*)d_in[5];
    const int*   t_raw   = (const int*)d_in[6];

    // 16 * 2^20 spatial / 8 per thread = 2,097,152 threads
    qpost_kernel<<<8192, 256>>>(log_x_t, log_x_0, (float*)d_out,
                                t_raw, la, l1a, lab, l1ab);
}

// round 9
// speedup vs baseline: 1.0091x; 1.0085x over previous
#include <cuda_runtime.h>
#include <math.h>

// Prob-space per-batch params (lane 0 of each warp computes, shfl-broadcast):
//  ab = exp(log_alpha_bars[t-1]),  c = 0.5*exp(log_1m_alpha_bars[t-1])
//  Qh = alpha + (1-alpha)/2       (x_t one-hot "hit" class), alpha = exp(la[t])
//  Ql = 1e-30*alpha + (1-alpha)/2 (x_t "miss" class)
//  posterior_k ∝ (ab*p0_k + c) * Q_k ; normalize via rcp; back to log.
//  t==0 (warp-uniform): posterior = normalize(log_x_0 + one_step) in log space.

__global__ void __launch_bounds__(256) qpost_kernel(const float* __restrict__ xt,
                                                    const float* __restrict__ x0,
                                                    float* __restrict__ out,
                                                    const int* __restrict__ t_raw,
                                                    const float* __restrict__ la,
                                                    const float* __restrict__ l1a,
                                                    const float* __restrict__ lab,
                                                    const float* __restrict__ l1ab) {
    unsigned tid = blockIdx.x * 256u + threadIdx.x;
    size_t e = (size_t)tid << 3;                   // 8 spatial elems per thread
    unsigned b = (unsigned)(e >> 20);              // batch (uniform per block)
    size_t base = ((size_t)b << 21) + (e & (((size_t)1 << 20) - 1));
    const size_t cstr = (size_t)1 << 20;           // class stride

    // ---- lane-0 param loads FIRST (L1-hit scalars at the queue head) ----
    float v_la = 0.f, v_l1a = 0.f, v_lab = 0.f, v_l1ab = 0.f;
    int t = 0;
    if ((threadIdx.x & 31) == 0) {
        // int64-vs-int32 sniff: 4 high words (t in [0,1000); FP ~1e-12, fixed data)
        int hw = t_raw[1] | t_raw[3] | t_raw[5] | t_raw[7];
        t = (hw == 0) ? t_raw[2 * b] : t_raw[b];
        v_la   = la[t];
        v_l1a  = l1a[t];
        int tm = (t > 0) ? (t - 1) : 0;
        v_lab  = lab[tm];
        v_l1ab = l1ab[tm];
    }

    // ---- front-batched streaming loads (independent of params) ----
    float4 xtA = __ldcs((const float4*)(xt + base));
    float4 xtB = __ldcs((const float4*)(xt + base + 4));
    float4 x0A = __ldcs((const float4*)(x0 + base));
    float4 x0B = __ldcs((const float4*)(x0 + base + 4));

    // ---- finish params on lane 0, broadcast (overlaps the load stall) ----
    float Qh = 0.f, Ql = 0.f, ab = 0.f, c = 0.f;
    if ((threadIdx.x & 31) == 0) {
        float alpha = __expf(v_la);
        float oma   = __expf(v_l1a);               // 1 - alpha (+1e-40)
        Qh = fmaf(0.5f, oma, alpha);
        Ql = fmaf(0.5f, oma, 1e-30f * alpha);
        ab = __expf(v_lab);
        c  = 0.5f * __expf(v_l1ab);
    }
    Qh = __shfl_sync(0xFFFFFFFFu, Qh, 0);
    Ql = __shfl_sync(0xFFFFFFFFu, Ql, 0);
    ab = __shfl_sync(0xFFFFFFFFu, ab, 0);
    c  = __shfl_sync(0xFFFFFFFFu, c,  0);
    t  = __shfl_sync(0xFFFFFFFFu, t,  0);
    float abc = ab + c;

    if (t != 0) {
        #pragma unroll
        for (int h = 0; h < 2; h++) {
            float4 xq = h ? xtB : xtA;
            float4 pq = h ? x0B : x0A;
            float4 o0, o1;
            #pragma unroll
            for (int k = 0; k < 4; k++) {
                float e0 = __expf(((const float*)&pq)[k]);  // exp(x01)=1-e0 (K=2)
                float f0 = fmaf(ab, e0, c);
                float f1 = fmaf(-ab, e0, abc);
                bool hi = (((const float*)&xq)[k] > -1.0f); // one-hot hit on c0?
                float w0 = f0 * (hi ? Qh : Ql);
                float w1 = f1 * (hi ? Ql : Qh);
                float r = __fdividef(1.0f, w0 + w1);
                ((float*)&o0)[k] = __logf(w0 * r);
                ((float*)&o1)[k] = __logf(w1 * r);
            }
            // plain write-back stores (test: better L2->DRAM drain than .cs)
            *((float4*)(out + base + 4 * h))        = o0;
            *((float4*)(out + base + cstr + 4 * h)) = o1;
        }
    } else {
        // t==0 (rare): posterior mean = log_x_0 exactly; need true class-1.
        float Lh = __logf(Qh);
        float Ll = __logf(Ql);
        float4 x1A = __ldcs((const float4*)(x0 + base + cstr));
        float4 x1B = __ldcs((const float4*)(x0 + base + cstr + 4));
        #pragma unroll
        for (int h = 0; h < 2; h++) {
            float4 xq = h ? xtB : xtA;
            float4 p0 = h ? x0B : x0A;
            float4 p1 = h ? x1B : x1A;
            float4 o0, o1;
            #pragma unroll
            for (int k = 0; k < 4; k++) {
                bool hi = (((const float*)&xq)[k] > -1.0f);
                float u0 = ((const float*)&p0)[k] + (hi ? Lh : Ll);
                float u1 = ((const float*)&p1)[k] + (hi ? Ll : Lh);
                float m = fmaxf(u0, u1);
                float l = m + __logf(1.0f + __expf(fminf(u0, u1) - m));
                ((float*)&o0)[k] = u0 - l;
                ((float*)&o1)[k] = u1 - l;
            }
            *((float4*)(out + base + 4 * h))        = o0;
            *((float4*)(out + base + cstr + 4 * h)) = o1;
        }
    }
}

extern "C" void kernel_launch(void* const* d_in, const int* in_sizes, int n_in,
                              void* d_out, int out_size) {
    const float* log_x_t = (const float*)d_in[0];
    const float* log_x_0 = (const float*)d_in[1];
    const float* la      = (const float*)d_in[2];
    const float* l1a     = (const float*)d_in[3];
    const float* lab     = (const float*)d_in[4];
    const float* l1ab    = (const float*)d_in[5];
    const int*   t_raw   = (const int*)d_in[6];

    // 16 * 2^20 spatial / 8 per thread = 2,097,152 threads
    qpost_kernel<<<8192, 256>>>(log_x_t, log_x_0, (float*)d_out,
                                t_raw, la, l1a, lab, l1ab);
}